// round 14
// baseline (speedup 1.0000x reference)
#include <cuda_runtime.h>

// Problem shape (fixed by the dataset)
#define BB 64
#define LL 4096
#define EE 256
#define HH 256
#define SPLITS 9             // 64*9 = 576 CTAs = one wave at 4 CTAs/SM (592 slots)
#define NW 8                 // warps per CTA
#define PRE 32               // rows prefetched via cp.async during the Wh phase
#define NPROD 8              // producers per batch-group (s < 8)
#define BGRP 8               // batches per producer group

// Scratch (no allocations allowed in kernel_launch).
// Counters padded to 128B stride to avoid L2-line sharing across batches.
__device__ float g_Wh[BB * EE];
__device__ float g_pm[BB * SPLITS];
__device__ float g_pd[BB * SPLITS];
__device__ float g_pctx[BB * SPLITS * EE];
__device__ int   g_whcnt[BB * 32];       // Wh-producers-done counter (stride 32)
__device__ int   g_cnt[BB * 32];         // splits-done counter (stride 32)

// ---------------- helpers ----------------
__device__ __forceinline__ unsigned smem_u32(const void* p) {
    return (unsigned)__cvta_generic_to_shared(p);
}
__device__ __forceinline__ void cp_async16(unsigned dst, const void* src) {
    asm volatile("cp.async.cg.shared.global [%0], [%1], 16;"
                 :: "r"(dst), "l"(src) : "memory");
}
__device__ __forceinline__ void cp_async_commit() {
    asm volatile("cp.async.commit_group;" ::: "memory");
}
__device__ __forceinline__ void cp_async_wait0() {
    asm volatile("cp.async.wait_group 0;" ::: "memory");
}

// interleaved dual butterfly reduce (two independent chains)
__device__ __forceinline__ void bfly2(float& pA, float& pB) {
#pragma unroll
    for (int sh = 16; sh >= 1; sh >>= 1) {
        pA += __shfl_xor_sync(0xffffffffu, pA, sh);
        pB += __shfl_xor_sync(0xffffffffu, pB, sh);
    }
}

// online-softmax accumulate of one row
__device__ __forceinline__ void online_upd(float p, const float4& v0, const float4& v1,
                                           float& m, float& d, float4& c0, float4& c1) {
    if (p > m) {
        const float sc = __expf(m - p);
        d *= sc;
        c0.x *= sc; c0.y *= sc; c0.z *= sc; c0.w *= sc;
        c1.x *= sc; c1.y *= sc; c1.z *= sc; c1.w *= sc;
        m = p;
    }
    const float e = __expf(p - m);
    d += e;
    c0.x += e * v0.x; c0.y += e * v0.y; c0.z += e * v0.z; c0.w += e * v0.w;
    c1.x += e * v1.x; c1.y += e * v1.y; c1.z += e * v1.z; c1.w += e * v1.w;
}

// -------------------------------------------------------------------------
// Fully fused single kernel. One CTA = (split s, batch b), 8 warps,
// single wave (576 CTAs, all co-resident).
// Phase 0: cp.async the first PRE enc rows into smem (no register cost) so
//          DRAM streams during the Wh phase.
// Phase 1: b-tiled producers — only CTAs (s<8, b%8==0) compute Wh. Producer
//          (s, bg) computes e-slice [s*32, s*32+32) for batches bg..bg+7,
//          with its W rows register-resident (W read ONCE per producer:
//          chip-wide W traffic 2 MB instead of 16 MB). Publishes + bumps the
//          8 batch counters. Everyone spins until their batch counter == 8.
// Phase 2: consume the smem rows, then the R6-proven register-LDG streaming
//          mainloop with online softmax from row PRE on.
// Phase 3: CTA combine -> split partials; last CTA per batch combines all
//          splits, writes out, resets counters (graph-replay clean).
// -------------------------------------------------------------------------
__global__ __launch_bounds__(256, 4) void k_fused(const float* __restrict__ W,
                                                  const float* __restrict__ hidden,
                                                  const float* __restrict__ enc,
                                                  float* __restrict__ out) {
    const int s = blockIdx.x;
    const int b = blockIdx.y;
    const int t = threadIdx.x;
    const int w = t >> 5;
    const int lane = t & 31;

    __shared__ float4 pre_s[PRE * (EE / 4)];   // 32 KB prefetch staging
    __shared__ float4 wh_s[EE / 4];
    __shared__ float sm_m[NW];
    __shared__ float sm_d[NW];
    __shared__ float sm_ctx[NW][EE];
    __shared__ int s_last;

    const float4* encb = reinterpret_cast<const float4*>(enc)
                       + (size_t)b * LL * (EE / 4);
    const int begin = (s * LL) / SPLITS;
    const int end   = ((s + 1) * LL) / SPLITS;
    // rows per split is 455/456, always > PRE

    // ---- Phase 0: fire the smem prefetch of rows [begin, begin+PRE) ----
    {
        const char* src = reinterpret_cast<const char*>(encb + (size_t)begin * (EE / 4));
        const unsigned dst = smem_u32(pre_s);
#pragma unroll
        for (int i = 0; i < (PRE * EE * 4) / (256 * 16); i++) {   // 8 chunks
            const unsigned off = (unsigned)i * (256 * 16) + (unsigned)t * 16;
            cp_async16(dst + off, src + off);
        }
        cp_async_commit();
    }

    // ---- Phase 1: b-tiled Wh producers (overlaps the in-flight cp.async) ----
    const int bg = b & ~(BGRP - 1);              // batch-group base
    if (s < NPROD && (b & (BGRP - 1)) == 0) {
        // warp w owns e = s*32 + w*4 + {0..3}; W rows register-resident
        const int e0 = s * 32 + w * 4;
        float4 wr0[4], wr1[4];
#pragma unroll
        for (int k = 0; k < 4; k++) {
            const float4* Wr = reinterpret_cast<const float4*>(W + (size_t)(e0 + k) * HH);
            wr0[k] = __ldg(Wr + lane);
            wr1[k] = __ldg(Wr + lane + 32);
        }
#pragma unroll
        for (int j = 0; j < BGRP; j++) {
            const float4* hv = reinterpret_cast<const float4*>(hidden + (size_t)(bg + j) * HH);
            const float4 h0 = __ldg(hv + lane);
            const float4 h1 = __ldg(hv + lane + 32);
            float p[4];
#pragma unroll
            for (int k = 0; k < 4; k++) {
                p[k] = wr0[k].x * h0.x + wr0[k].y * h0.y + wr0[k].z * h0.z + wr0[k].w * h0.w
                     + wr1[k].x * h1.x + wr1[k].y * h1.y + wr1[k].z * h1.z + wr1[k].w * h1.w;
            }
#pragma unroll
            for (int sh = 16; sh >= 1; sh >>= 1) {
#pragma unroll
                for (int k = 0; k < 4; k++)
                    p[k] += __shfl_xor_sync(0xffffffffu, p[k], sh);
            }
            if (lane < 4)
                g_Wh[(bg + j) * EE + e0 + lane] = p[lane];
        }
        __threadfence();     // publish all Wh stores (release)
        __syncthreads();     // all warps of this producer published
        if (t < BGRP)
            atomicAdd(&g_whcnt[(bg + t) * 32], 1);
    }

    // ---- rendezvous: wait until all NPROD producers of batch b published ----
    if (t == 0) {
        volatile int* cnt = &g_whcnt[b * 32];
        while (*cnt < NPROD) { __nanosleep(64); }
    }
    __syncthreads();
    __threadfence();         // acquire: producers' Wh stores visible

    // load full Wh[b] into smem (L2-hot), then registers
    if (t < EE / 4)
        wh_s[t] = reinterpret_cast<const float4*>(g_Wh + b * EE)[t];
    cp_async_wait0();        // prefetched rows landed (own group)
    __syncthreads();         // ... and visible CTA-wide; wh_s ready

    const float4 wh0 = wh_s[lane];
    const float4 wh1 = wh_s[lane + 32];

    float m = -1e30f, d = 0.f;
    float4 c0 = make_float4(0.f, 0.f, 0.f, 0.f);
    float4 c1 = make_float4(0.f, 0.f, 0.f, 0.f);

    // prime the steady-state register pipeline (rows PRE+w, PRE+w+8)
    int  l  = begin + PRE + w;
    bool hA = l < end;
    bool hB = l + 8 < end;
    float4 a0, a1, b0, b1;
    if (hA) {
        const float4* p0 = encb + (size_t)l * (EE / 4);
        a0 = __ldcs(p0 + lane);
        a1 = __ldcs(p0 + lane + 32);
    }
    if (hB) {
        const float4* p1 = encb + (size_t)(l + 8) * (EE / 4);
        b0 = __ldcs(p1 + lane);
        b1 = __ldcs(p1 + lane + 32);
    }

    // ---- Phase 2a: consume the PRE smem rows (warp w: rows w+16j, w+8+16j) ----
#pragma unroll
    for (int j = 0; j < PRE / 16; j++) {
        const int rA = w + 16 * j;
        const int rB = rA + 8;
        const float4 sa0 = pre_s[rA * (EE / 4) + lane];
        const float4 sa1 = pre_s[rA * (EE / 4) + lane + 32];
        const float4 sb0 = pre_s[rB * (EE / 4) + lane];
        const float4 sb1 = pre_s[rB * (EE / 4) + lane + 32];

        float pA = sa0.x * wh0.x + sa0.y * wh0.y + sa0.z * wh0.z + sa0.w * wh0.w
                 + sa1.x * wh1.x + sa1.y * wh1.y + sa1.z * wh1.z + sa1.w * wh1.w;
        float pB = sb0.x * wh0.x + sb0.y * wh0.y + sb0.z * wh0.z + sb0.w * wh0.w
                 + sb1.x * wh1.x + sb1.y * wh1.y + sb1.z * wh1.z + sb1.w * wh1.w;
        bfly2(pA, pB);
        online_upd(pA, sa0, sa1, m, d, c0, c1);
        online_upd(pB, sb0, sb1, m, d, c0, c1);
    }

    // ---- Phase 2b: steady-state mainloop (R6 structure) from row PRE ----
    while (hA) {
        const int nl = l + 16;
        const bool nA = nl < end;
        const bool nB = nl + 8 < end;
        float4 na0, na1, nb0, nb1;
        if (nA) {
            const float4* p0 = encb + (size_t)nl * (EE / 4);
            na0 = __ldcs(p0 + lane);
            na1 = __ldcs(p0 + lane + 32);
        }
        if (nB) {
            const float4* p1 = encb + (size_t)(nl + 8) * (EE / 4);
            nb0 = __ldcs(p1 + lane);
            nb1 = __ldcs(p1 + lane + 32);
        }

        float pA = a0.x * wh0.x + a0.y * wh0.y + a0.z * wh0.z + a0.w * wh0.w
                 + a1.x * wh1.x + a1.y * wh1.y + a1.z * wh1.z + a1.w * wh1.w;
        float pB = 0.f;
        if (hB)
            pB = b0.x * wh0.x + b0.y * wh0.y + b0.z * wh0.z + b0.w * wh0.w
               + b1.x * wh1.x + b1.y * wh1.y + b1.z * wh1.z + b1.w * wh1.w;
        bfly2(pA, pB);

        online_upd(pA, a0, a1, m, d, c0, c1);
        if (hB) online_upd(pB, b0, b1, m, d, c0, c1);

        a0 = na0; a1 = na1; b0 = nb0; b1 = nb1;
        hA = nA; hB = nB; l = nl;
    }

    // ---- Phase 3: CTA-level combine ----
    if (lane == 0) { sm_m[w] = m; sm_d[w] = d; }
    __syncthreads();

    float M = sm_m[0];
#pragma unroll
    for (int i = 1; i < NW; i++) M = fmaxf(M, sm_m[i]);
    float D = 0.f;
#pragma unroll
    for (int i = 0; i < NW; i++) D += sm_d[i] * __expf(sm_m[i] - M);

    const float sc = __expf(m - M);   // m is warp-uniform after butterfly
    sm_ctx[w][lane * 4 + 0] = c0.x * sc;
    sm_ctx[w][lane * 4 + 1] = c0.y * sc;
    sm_ctx[w][lane * 4 + 2] = c0.z * sc;
    sm_ctx[w][lane * 4 + 3] = c0.w * sc;
    sm_ctx[w][128 + lane * 4 + 0] = c1.x * sc;
    sm_ctx[w][128 + lane * 4 + 1] = c1.y * sc;
    sm_ctx[w][128 + lane * 4 + 2] = c1.z * sc;
    sm_ctx[w][128 + lane * 4 + 3] = c1.w * sc;
    __syncthreads();

    float acc = 0.f;
#pragma unroll
    for (int i = 0; i < NW; i++) acc += sm_ctx[i][t];

    const int idx = b * SPLITS + s;
    g_pctx[(size_t)idx * EE + t] = acc;
    if (t == 0) { g_pm[idx] = M; g_pd[idx] = D; }

    // ---- fused split-combine: last CTA of this batch finishes the output ----
    __threadfence();
    if (t == 0) {
        const int old = atomicAdd(&g_cnt[b * 32], 1);
        s_last = (old == SPLITS - 1);
    }
    __syncthreads();
    if (!s_last) return;
    __threadfence();   // acquire: other CTAs' partials visible

    float pm[SPLITS];
#pragma unroll
    for (int i = 0; i < SPLITS; i++) pm[i] = g_pm[b * SPLITS + i];
    float Mg = pm[0];
#pragma unroll
    for (int i = 1; i < SPLITS; i++) Mg = fmaxf(Mg, pm[i]);
    float Dg = 0.f;
#pragma unroll
    for (int i = 0; i < SPLITS; i++) Dg += g_pd[b * SPLITS + i] * __expf(pm[i] - Mg);

    float accg = 0.f;
#pragma unroll
    for (int i = 0; i < SPLITS; i++)
        accg += g_pctx[(size_t)(b * SPLITS + i) * EE + t] * __expf(pm[i] - Mg);

    out[b * EE + t] = accg / Dg;

    // clean state for next graph replay
    if (t == 0) {
        g_cnt[b * 32] = 0;
        g_whcnt[b * 32] = 0;
    }
}

// -------------------------------------------------------------------------
// Inputs (metadata order): hidden [B,H] f32, encoderhidden [B,L,E] f32,
// W [E,H] f32, b [1] f32 (softmax-invariant -> ignored).
// Output: context [B,E] f32.
// -------------------------------------------------------------------------
extern "C" void kernel_launch(void* const* d_in, const int* in_sizes, int n_in,
                              void* d_out, int out_size) {
    const float* hidden = (const float*)d_in[0];
    const float* enc    = (const float*)d_in[1];
    const float* W      = (const float*)d_in[2];
    float* out          = (float*)d_out;

    k_fused<<<dim3(SPLITS, BB), 256>>>(W, hidden, enc, out);
}

// round 15
// speedup vs baseline: 1.0494x; 1.0494x over previous
#include <cuda_runtime.h>

// Problem shape (fixed by the dataset)
#define BB 64
#define LL 4096
#define EE 256
#define HH 256
#define SPLITS 9             // 64*9 = 576 CTAs = one wave at 4 CTAs/SM (592 slots)
#define NW 8                 // warps per CTA
#define PRE 32               // rows prefetched via cp.async before the PDL sync

// Scratch (no allocations allowed in kernel_launch).
__device__ float g_Wh[BB * EE];
__device__ float g_pm[BB * SPLITS];
__device__ float g_pd[BB * SPLITS];
__device__ float g_pctx[BB * SPLITS * EE];
__device__ int   g_cnt[BB * 32];         // splits-done counter (stride 32)

// ---------------- helpers ----------------
__device__ __forceinline__ unsigned smem_u32(const void* p) {
    return (unsigned)__cvta_generic_to_shared(p);
}
__device__ __forceinline__ void cp_async16(unsigned dst, const void* src) {
    asm volatile("cp.async.cg.shared.global [%0], [%1], 16;"
                 :: "r"(dst), "l"(src) : "memory");
}
__device__ __forceinline__ void cp_async_commit() {
    asm volatile("cp.async.commit_group;" ::: "memory");
}
__device__ __forceinline__ void cp_async_wait0() {
    asm volatile("cp.async.wait_group 0;" ::: "memory");
}

// interleaved dual butterfly reduce (two independent chains)
__device__ __forceinline__ void bfly2(float& pA, float& pB) {
#pragma unroll
    for (int sh = 16; sh >= 1; sh >>= 1) {
        pA += __shfl_xor_sync(0xffffffffu, pA, sh);
        pB += __shfl_xor_sync(0xffffffffu, pB, sh);
    }
}

// online-softmax accumulate of one row
__device__ __forceinline__ void online_upd(float p, const float4& v0, const float4& v1,
                                           float& m, float& d, float4& c0, float4& c1) {
    if (p > m) {
        const float sc = __expf(m - p);
        d *= sc;
        c0.x *= sc; c0.y *= sc; c0.z *= sc; c0.w *= sc;
        c1.x *= sc; c1.y *= sc; c1.z *= sc; c1.w *= sc;
        m = p;
    }
    const float e = __expf(p - m);
    d += e;
    c0.x += e * v0.x; c0.y += e * v0.y; c0.z += e * v0.z; c0.w += e * v0.w;
    c1.x += e * v1.x; c1.y += e * v1.y; c1.z += e * v1.z; c1.w += e * v1.w;
}

// -------------------------------------------------------------------------
// k0: Wh[b,e] = sum_h W[e,h] * hidden[b,h]. One warp per 4 e's (4 ILP
// shuffle chains). Triggers programmatic launch completion IMMEDIATELY so
// k1 starts launching (and prefetching enc) concurrently with this compute.
// Also zeroes the split-combine counters. grid = (8, 64), block = 256.
// -------------------------------------------------------------------------
__global__ __launch_bounds__(256) void k0_wh(const float* __restrict__ W,
                                             const float* __restrict__ hidden) {
    cudaTriggerProgrammaticLaunchCompletion();   // license k1 launch NOW

    const int b = blockIdx.y;
    const int t = threadIdx.x;
    const int w = t >> 5;
    const int lane = t & 31;

    if (blockIdx.x == 0 && t == 0) g_cnt[b * 32] = 0;

    const int e0 = (blockIdx.x * NW + w) * 4;
    const float4* hv = reinterpret_cast<const float4*>(hidden + (size_t)b * HH);
    const float4 h0 = __ldg(hv + lane);
    const float4 h1 = __ldg(hv + lane + 32);

    float p[4];
#pragma unroll
    for (int i = 0; i < 4; i++) {
        const float4* Wr = reinterpret_cast<const float4*>(W + (size_t)(e0 + i) * HH);
        const float4 w0 = __ldg(Wr + lane);
        const float4 w1 = __ldg(Wr + lane + 32);
        p[i] = w0.x * h0.x + w0.y * h0.y + w0.z * h0.z + w0.w * h0.w
             + w1.x * h1.x + w1.y * h1.y + w1.z * h1.z + w1.w * h1.w;
    }
#pragma unroll
    for (int sh = 16; sh >= 1; sh >>= 1) {
#pragma unroll
        for (int i = 0; i < 4; i++)
            p[i] += __shfl_xor_sync(0xffffffffu, p[i], sh);
    }
    if (lane < 4) g_Wh[b * EE + e0 + lane] = p[lane];
}

// -------------------------------------------------------------------------
// k1: launched with PDL. Phase 0 prefetches PRE enc rows via cp.async
// (overlapping k0's compute + the launch ramp), then griddepcontrol-waits
// for k0 completion, then runs the R13-proven streaming mainloop + fused
// split-combine. One CTA = (split s, batch b), single wave.
// -------------------------------------------------------------------------
__global__ __launch_bounds__(256, 4) void k1_pass(const float* __restrict__ enc,
                                                  float* __restrict__ out) {
    const int s = blockIdx.x;
    const int b = blockIdx.y;
    const int t = threadIdx.x;
    const int w = t >> 5;
    const int lane = t & 31;

    __shared__ float4 pre_s[PRE * (EE / 4)];   // 32 KB prefetch staging
    __shared__ float4 wh_s[EE / 4];
    __shared__ float sm_m[NW];
    __shared__ float sm_d[NW];
    __shared__ float sm_ctx[NW][EE];
    __shared__ int s_last;

    const float4* encb = reinterpret_cast<const float4*>(enc)
                       + (size_t)b * LL * (EE / 4);
    const int begin = (s * LL) / SPLITS;
    const int end   = ((s + 1) * LL) / SPLITS;
    // rows per split is 455/456, always > PRE

    // ---- Phase 0: fire the smem prefetch of rows [begin, begin+PRE) ----
    {
        const char* src = reinterpret_cast<const char*>(encb + (size_t)begin * (EE / 4));
        const unsigned dst = smem_u32(pre_s);
#pragma unroll
        for (int i = 0; i < (PRE * EE * 4) / (256 * 16); i++) {   // 8 chunks
            const unsigned off = (unsigned)i * (256 * 16) + (unsigned)t * 16;
            cp_async16(dst + off, src + off);
        }
        cp_async_commit();
    }

    // ---- HW wait for k0 completion (g_Wh ready) ----
    cudaGridDependencySynchronize();

    // load full Wh[b] into smem (L2-hot), then registers
    if (t < EE / 4)
        wh_s[t] = reinterpret_cast<const float4*>(g_Wh + b * EE)[t];
    cp_async_wait0();        // prefetched rows landed (own group)
    __syncthreads();         // ... and visible CTA-wide; wh_s ready

    const float4 wh0 = wh_s[lane];
    const float4 wh1 = wh_s[lane + 32];

    float m = -1e30f, d = 0.f;
    float4 c0 = make_float4(0.f, 0.f, 0.f, 0.f);
    float4 c1 = make_float4(0.f, 0.f, 0.f, 0.f);

    // prime the steady-state register pipeline (rows PRE+w, PRE+w+8)
    int  l  = begin + PRE + w;
    bool hA = l < end;
    bool hB = l + 8 < end;
    float4 a0, a1, b0, b1;
    if (hA) {
        const float4* p0 = encb + (size_t)l * (EE / 4);
        a0 = __ldcs(p0 + lane);
        a1 = __ldcs(p0 + lane + 32);
    }
    if (hB) {
        const float4* p1 = encb + (size_t)(l + 8) * (EE / 4);
        b0 = __ldcs(p1 + lane);
        b1 = __ldcs(p1 + lane + 32);
    }

    // ---- Phase 2a: consume the PRE smem rows (warp w: rows w+16j, w+8+16j) ----
#pragma unroll
    for (int j = 0; j < PRE / 16; j++) {
        const int rA = w + 16 * j;
        const int rB = rA + 8;
        const float4 sa0 = pre_s[rA * (EE / 4) + lane];
        const float4 sa1 = pre_s[rA * (EE / 4) + lane + 32];
        const float4 sb0 = pre_s[rB * (EE / 4) + lane];
        const float4 sb1 = pre_s[rB * (EE / 4) + lane + 32];

        float pA = sa0.x * wh0.x + sa0.y * wh0.y + sa0.z * wh0.z + sa0.w * wh0.w
                 + sa1.x * wh1.x + sa1.y * wh1.y + sa1.z * wh1.z + sa1.w * wh1.w;
        float pB = sb0.x * wh0.x + sb0.y * wh0.y + sb0.z * wh0.z + sb0.w * wh0.w
                 + sb1.x * wh1.x + sb1.y * wh1.y + sb1.z * wh1.z + sb1.w * wh1.w;
        bfly2(pA, pB);
        online_upd(pA, sa0, sa1, m, d, c0, c1);
        online_upd(pB, sb0, sb1, m, d, c0, c1);
    }

    // ---- Phase 2b: steady-state mainloop (R6 structure) from row PRE ----
    while (hA) {
        const int nl = l + 16;
        const bool nA = nl < end;
        const bool nB = nl + 8 < end;
        float4 na0, na1, nb0, nb1;
        if (nA) {
            const float4* p0 = encb + (size_t)nl * (EE / 4);
            na0 = __ldcs(p0 + lane);
            na1 = __ldcs(p0 + lane + 32);
        }
        if (nB) {
            const float4* p1 = encb + (size_t)(nl + 8) * (EE / 4);
            nb0 = __ldcs(p1 + lane);
            nb1 = __ldcs(p1 + lane + 32);
        }

        float pA = a0.x * wh0.x + a0.y * wh0.y + a0.z * wh0.z + a0.w * wh0.w
                 + a1.x * wh1.x + a1.y * wh1.y + a1.z * wh1.z + a1.w * wh1.w;
        float pB = 0.f;
        if (hB)
            pB = b0.x * wh0.x + b0.y * wh0.y + b0.z * wh0.z + b0.w * wh0.w
               + b1.x * wh1.x + b1.y * wh1.y + b1.z * wh1.z + b1.w * wh1.w;
        bfly2(pA, pB);

        online_upd(pA, a0, a1, m, d, c0, c1);
        if (hB) online_upd(pB, b0, b1, m, d, c0, c1);

        a0 = na0; a1 = na1; b0 = nb0; b1 = nb1;
        hA = nA; hB = nB; l = nl;
    }

    // ---- Phase 3: CTA-level combine ----
    if (lane == 0) { sm_m[w] = m; sm_d[w] = d; }
    __syncthreads();

    float M = sm_m[0];
#pragma unroll
    for (int i = 1; i < NW; i++) M = fmaxf(M, sm_m[i]);
    float D = 0.f;
#pragma unroll
    for (int i = 0; i < NW; i++) D += sm_d[i] * __expf(sm_m[i] - M);

    const float sc = __expf(m - M);   // m is warp-uniform after butterfly
    sm_ctx[w][lane * 4 + 0] = c0.x * sc;
    sm_ctx[w][lane * 4 + 1] = c0.y * sc;
    sm_ctx[w][lane * 4 + 2] = c0.z * sc;
    sm_ctx[w][lane * 4 + 3] = c0.w * sc;
    sm_ctx[w][128 + lane * 4 + 0] = c1.x * sc;
    sm_ctx[w][128 + lane * 4 + 1] = c1.y * sc;
    sm_ctx[w][128 + lane * 4 + 2] = c1.z * sc;
    sm_ctx[w][128 + lane * 4 + 3] = c1.w * sc;
    __syncthreads();

    float acc = 0.f;
#pragma unroll
    for (int i = 0; i < NW; i++) acc += sm_ctx[i][t];

    const int idx = b * SPLITS + s;
    g_pctx[(size_t)idx * EE + t] = acc;
    if (t == 0) { g_pm[idx] = M; g_pd[idx] = D; }

    // ---- fused split-combine: last CTA of this batch finishes the output ----
    __threadfence();
    if (t == 0) {
        const int old = atomicAdd(&g_cnt[b * 32], 1);
        s_last = (old == SPLITS - 1);
    }
    __syncthreads();
    if (!s_last) return;
    __threadfence();   // acquire: other CTAs' partials visible

    float pm[SPLITS];
#pragma unroll
    for (int i = 0; i < SPLITS; i++) pm[i] = g_pm[b * SPLITS + i];
    float Mg = pm[0];
#pragma unroll
    for (int i = 1; i < SPLITS; i++) Mg = fmaxf(Mg, pm[i]);
    float Dg = 0.f;
#pragma unroll
    for (int i = 0; i < SPLITS; i++) Dg += g_pd[b * SPLITS + i] * __expf(pm[i] - Mg);

    float accg = 0.f;
#pragma unroll
    for (int i = 0; i < SPLITS; i++)
        accg += g_pctx[(size_t)(b * SPLITS + i) * EE + t] * __expf(pm[i] - Mg);

    out[b * EE + t] = accg / Dg;

    // clean state for next graph replay (k0 also zeroes at start)
    if (t == 0) g_cnt[b * 32] = 0;
}

// -------------------------------------------------------------------------
// Inputs (metadata order): hidden [B,H] f32, encoderhidden [B,L,E] f32,
// W [E,H] f32, b [1] f32 (softmax-invariant -> ignored).
// Output: context [B,E] f32.
// -------------------------------------------------------------------------
extern "C" void kernel_launch(void* const* d_in, const int* in_sizes, int n_in,
                              void* d_out, int out_size) {
    const float* hidden = (const float*)d_in[0];
    const float* enc    = (const float*)d_in[1];
    const float* W      = (const float*)d_in[2];
    float* out          = (float*)d_out;

    // k0: normal launch
    k0_wh<<<dim3(EE / (NW * 4), BB), 256>>>(W, hidden);

    // k1: programmatic dependent launch — may start while k0 runs; each CTA
    // gates on k0 completion via cudaGridDependencySynchronize().
    cudaLaunchConfig_t cfg = {};
    cfg.gridDim  = dim3(SPLITS, BB);
    cfg.blockDim = dim3(256);
    cfg.dynamicSmemBytes = 0;
    cudaLaunchAttribute attrs[1];
    attrs[0].id = cudaLaunchAttributeProgrammaticStreamSerialization;
    attrs[0].val.programmaticStreamSerializationAllowed = 1;
    cfg.attrs = attrs;
    cfg.numAttrs = 1;
    cudaLaunchKernelEx(&cfg, k1_pass, enc, (float*)d_out);
}